// round 5
// baseline (speedup 1.0000x reference)
#include <cuda_runtime.h>
#include <cstdint>
#include <cstring>

#define NS    32768
#define NBITS 64
#define MG    8
#define HID   256
#define NC    100

typedef unsigned long long ull;

// ---------------------------------------------------------------------------
// Threefry-2x32, 20 rounds — bit-exact match of JAX's threefry2x32 primitive.
// ---------------------------------------------------------------------------
__host__ __device__ __forceinline__ void threefry2x32(
    uint32_t k0, uint32_t k1, uint32_t c0, uint32_t c1,
    uint32_t& o0, uint32_t& o1) {
  uint32_t ks2 = k0 ^ k1 ^ 0x1BD11BDAu;
  uint32_t x0 = c0 + k0;
  uint32_t x1 = c1 + k1;
#define TF_RND(r) { x0 += x1; x1 = (x1 << (r)) | (x1 >> (32 - (r))); x1 ^= x0; }
  TF_RND(13) TF_RND(15) TF_RND(26) TF_RND(6)
  x0 += k1;  x1 += ks2 + 1u;
  TF_RND(17) TF_RND(29) TF_RND(16) TF_RND(24)
  x0 += ks2; x1 += k0 + 2u;
  TF_RND(13) TF_RND(15) TF_RND(26) TF_RND(6)
  x0 += k0;  x1 += k1 + 3u;
  TF_RND(17) TF_RND(29) TF_RND(16) TF_RND(24)
  x0 += k1;  x1 += ks2 + 4u;
  TF_RND(13) TF_RND(15) TF_RND(26) TF_RND(6)
  x0 += ks2; x1 += k0 + 5u;
#undef TF_RND
  o0 = x0; o1 = x1;
}

// ---------------------------------------------------------------------------
// Device-global scratch
// ---------------------------------------------------------------------------
__device__ float g_xp  [NS * NBITS];
__device__ float g_xmap[NS * NBITS];
__device__ unsigned char g_target[NS * MG];
__device__ unsigned int  g_xbits[NS * 2];
__device__ int           g_K[NS];
__device__ unsigned char g_act[NS * NC];
__device__ unsigned char g_ct[NC * MG];
__device__ unsigned int  g_cbits[NC * 2];
__device__ double g_mapSum;
__device__ double g_netSum;
__device__ unsigned long long g_hits;
__device__ unsigned long long g_hamSum;
__device__ unsigned long long g_actTot;
__device__ int g_tmode;

__device__ __forceinline__ bool read_tpl(const void* p, int b) {
  if (g_tmode == 0) return ((const unsigned char*)p)[b] != 0;
  return ((const int*)p)[b] != 0;
}

// ---------------------------------------------------------------------------
// Kernel 1 (merged): accumulator init + template dtype detect + centroid prep
// ---------------------------------------------------------------------------
__global__ void setup_kernel(const float* __restrict__ cen,
                             const int* __restrict__ perm,
                             const unsigned char* tm, const unsigned char* tr) {
  __shared__ int permS[NBITS];
  int t = threadIdx.x;
  if (t < NBITS) permS[t] = perm[t];
  if (t == 0) {
    g_mapSum = 0.0; g_netSum = 0.0;
    g_hits = 0ull; g_hamSum = 0ull; g_actTot = 0ull;
    int has3F = 0, mis = 0;
    for (int i = 0; i < 64; i++) {
      unsigned char bm = tm[i], br = tr[i];
      if (bm == 0x3F || br == 0x3F) has3F = 1;
      if (i & 3) mis += (bm != 0) + (br != 0);
    }
    g_tmode = has3F ? 1 : (mis ? 0 : 1);
  }
  __syncthreads();
  if (t >= NC) return;
  unsigned int w0 = 0, w1 = 0;
  for (int b = 0; b < NBITS; b++) {
    bool bit = cen[t * NBITS + permS[b]] > 0.f;
    if (bit) { if (b < 32) w0 |= 1u << b; else w1 |= 1u << (b - 32); }
  }
  g_cbits[t * 2 + 0] = w0;
  g_cbits[t * 2 + 1] = w1;
  for (int m = 0; m < MG; m++) {
    unsigned int w = (m < 4) ? w0 : w1;
    g_ct[t * MG + m] = (unsigned char)((w >> ((m & 3) * 8)) & 0xffu);
  }
}

// ---------------------------------------------------------------------------
// Kernel 2: PRNG draws, stable argsort ranks, flips, targets, sign bits.
// ---------------------------------------------------------------------------
__global__ void prep_kernel(const float* __restrict__ x,
                            const int* __restrict__ perm,
                            const void* tmap, const void* traw,
                            uint32_t km0, uint32_t km1,
                            uint32_t kr0, uint32_t kr1) {
  __shared__ float xps[2][NBITS];
  __shared__ unsigned int us[2][2][NBITS];
  __shared__ int permS[NBITS];
  __shared__ int tposS[2][4];
  __shared__ int ranksS[2][2][4];
  __shared__ unsigned int rawb[2][2];
  __shared__ unsigned int xbw[2][2];

  int tid = threadIdx.x;
  if (tid < NBITS) permS[tid] = perm[tid];
  if (tid < 2) {
    const void* tp = (tid == 0) ? tmap : traw;
    int c = 0;
    for (int b = 0; b < NBITS; b++)
      if (read_tpl(tp, b)) { if (c < 4) tposS[tid][c] = b; c++; }
  }
  if (tid < 4) { rawb[tid >> 1][tid & 1] = 0u; xbw[tid >> 1][tid & 1] = 0u; }
  __syncthreads();

  int rid = tid >> 7;
  int sub = tid & 127;
  int op  = sub >> 6;
  int b   = sub & 63;
  int row = blockIdx.x * 2 + rid;

  if (op == 0) xps[rid][b] = x[row * NBITS + permS[b]];
  uint32_t k0 = op ? kr0 : km0;
  uint32_t k1 = op ? kr1 : km1;
  uint32_t o0, o1;
  threefry2x32(k0, k1, 0u, (uint32_t)(row * NBITS + b), o0, o1);
  us[rid][op][b] = (o0 ^ o1) >> 9;
  __syncthreads();

  if (b < 4) {
    int tpos = tposS[op][b];
    unsigned int ut = us[rid][op][tpos];
    int cnt = 0;
    for (int j = 0; j < NBITS; j++) {
      unsigned int uj = us[rid][op][j];
      cnt += (uj < ut) || (uj == ut && j < tpos);
    }
    ranksS[rid][op][b] = cnt;
  }
  __syncthreads();

  float v = xps[rid][b];
  bool flip = (b == ranksS[rid][op][0]) | (b == ranksS[rid][op][1]) |
              (b == ranksS[rid][op][2]) | (b == ranksS[rid][op][3]);
  if (op == 0) {
    g_xp  [row * NBITS + b] = v;
    g_xmap[row * NBITS + b] = flip ? -v : v;
    if (v > 0.f) atomicOr(&xbw[rid][b >> 5], 1u << (b & 31));
  } else {
    bool bit = flip ? (v < 0.f) : (v > 0.f);
    if (bit) atomicOr(&rawb[rid][b >> 5], 1u << (b & 31));
  }
  __syncthreads();

  if (op == 1 && b < MG) {
    unsigned int w = rawb[rid][b >> 2];
    g_target[row * MG + b] = (unsigned char)((w >> ((b & 3) * 8)) & 0xffu);
  }
  if (op == 0 && b < 2) g_xbits[row * 2 + b] = xbw[rid][b];
}

// ---------------------------------------------------------------------------
// Kernel 3: active-class compaction + exact hamming sums. 1 warp / row.
// ---------------------------------------------------------------------------
__global__ void ham_kernel(const int* __restrict__ y) {
  int tid = threadIdx.x, w = tid >> 5, l = tid & 31;
  int row = blockIdx.x * 8 + w;
  unsigned int xb0 = g_xbits[row * 2], xb1 = g_xbits[row * 2 + 1];
  int K = 0;
  unsigned long long hs = 0ull;
  for (int cb = 0; cb < 128; cb += 32) {
    int c = cb + l;
    bool act = (c < NC) && (y[row * NC + c] > 0);
    unsigned int msk = __ballot_sync(0xffffffffu, act);
    if (act) {
      int pos = K + __popc(msk & ((1u << l) - 1u));
      g_act[row * NC + pos] = (unsigned char)c;
      hs += (unsigned long long)(__popc(xb0 ^ g_cbits[c * 2]) +
                                 __popc(xb1 ^ g_cbits[c * 2 + 1]));
    }
    K += __popc(msk);
  }
  if (l == 0) g_K[row] = K;
  for (int o = 16; o; o >>= 1)
    hs += __shfl_xor_sync(0xffffffffu, hs, o);
  if (l == 0) {
    atomicAdd(&g_hamSum, hs);
    atomicAdd(&g_actTot, (unsigned long long)K);
  }
}

// ---------------------------------------------------------------------------
// Kernel 4: fused batched MLP + losses, FFMA2 with smem-duplicated W2.
//
// CTA: 256 thr = 8 warps; 64 rows; warp w owns rows [8w, 8w+8).
// Lane l owns cols {4l..4l+3} U {128+4l..+3}.
// W2 chunk staged DUPLICATED: word = k*512 + col*2, value (w,w) -> ulonglong2
//   LDS128 yields f32x2 W operands with zero MOVs.
// hT: float2 slot k*36 + ((w*4+ip)^(k>>3)) = rows (2ip,2ip+1) of warp w.
// acc2[ip][j]: f32x2 accumulating rows (2ip,2ip+1), col j.
// x held in registers (xperm), rebuilt per-m via shuffles.
// ---------------------------------------------------------------------------
#define SM_W1S   0          // 2048 floats
#define SM_B1    2048       // 256
#define SM_B2    2304       // 256
#define SM_WRED  2560       // 2048
#define SM_HT    4608       // 18432 (256 k * 36 float2)
#define SM_W2    23040      // 2 * 16384 (duplicated chunks)
#define SM_FLOATS 55808     // 223232 bytes

__device__ __forceinline__ void ffma2(ull& d, ull a, ull b) {
  asm("fma.rn.f32x2 %0, %1, %2, %0;" : "+l"(d) : "l"(a), "l"(b));
}
__device__ __forceinline__ float2 unpack2(ull v) {
  float2 t;
  asm("mov.b64 {%0, %1}, %2;" : "=f"(t.x), "=f"(t.y) : "l"(v));
  return t;
}
__device__ __forceinline__ float fast_rcp(float d) {
  float r = __uint_as_float(0x7EF311C3u - __float_as_uint(d));
  r = r * (2.0f - d * r);
  r = r * (2.0f - d * r);
  r = r * (2.0f - d * r);
  return r;
}

__global__ void __launch_bounds__(256)
mlp_kernel(const float* __restrict__ W1, const float* __restrict__ b1,
           const float* __restrict__ W2, const float* __restrict__ b2) {
  extern __shared__ float sm[];
  float* W1s   = sm + SM_W1S;
  float* b1s   = sm + SM_B1;
  float* b2s   = sm + SM_B2;
  float* wred  = sm + SM_WRED;
  float* hT    = sm + SM_HT;
  float* w2dup = sm + SM_W2;

  int tid = threadIdx.x, w = tid >> 5, l = tid & 31;
  int pass = blockIdx.y;
  int row0 = blockIdx.x * 64;
  const float* inp = (pass == 0) ? g_xmap : g_xp;
  const int w4 = w * 4;

  // x rows of this warp into registers: lane l holds cols (2l, 2l+1) x 8 rows
  float xperm[16];
#pragma unroll
  for (int r = 0; r < 8; r++) {
    float2 t = *(const float2*)(inp + (row0 + w * 8 + r) * NBITS + 2 * l);
    xperm[2 * r] = t.x; xperm[2 * r + 1] = t.y;
  }

  // stage chunk 0 of W2 (duplicated) into buffer 0
  {
    const float4* src = (const float4*)W2;
#pragma unroll
    for (int q = 0; q < 8; q++) {
      float4 v = src[tid + q * 256];
      int e = tid + q * 256;           // float4 index within chunk
      int k2 = e >> 6;                 // k row (0..31)
      int cc = (e & 63) * 4;           // starting col
      float* dst = w2dup + k2 * 512 + cc * 2;
      *(float4*)(dst)     = make_float4(v.x, v.x, v.y, v.y);
      *(float4*)(dst + 4) = make_float4(v.z, v.z, v.w, v.w);
    }
  }

  double mapAcc = 0.0, netAcc = 0.0;
  unsigned int hitAcc = 0;

  for (int mm = 0; mm < MG; mm++) {
    __syncthreads();
    {
      const float4* w1p = (const float4*)(W1 + mm * 2048);
      float4* w1d = (float4*)W1s;
      w1d[tid] = w1p[tid];
      w1d[tid + 256] = w1p[tid + 256];
      b1s[tid] = b1[mm * 256 + tid];
      b2s[tid] = b2[mm * 256 + tid];
    }
    __syncthreads();

    // ---- GEMM1: h = silu(xs @ W1 + b1) -> transposed swizzled hT ----
    {
      float xv[8][8];
#pragma unroll
      for (int i = 0; i < 8; i++)
#pragma unroll
        for (int s = 0; s < 8; s++)
          xv[i][s] = __shfl_sync(0xffffffffu, xperm[2 * i + (s & 1)],
                                 mm * 4 + (s >> 1));
#pragma unroll
      for (int kk = 0; kk < 8; kk++) {
        int k = kk * 32 + l;
        float w1c[8];
#pragma unroll
        for (int s = 0; s < 8; s++) w1c[s] = W1s[s * 256 + k];
        float bk = b1s[k];
        float h[8];
#pragma unroll
        for (int i = 0; i < 8; i++) {
          float a = bk;
#pragma unroll
          for (int s = 0; s < 8; s++) a = fmaf(xv[i][s], w1c[s], a);
          float t = __expf(-a);
          float d = 1.0f + fminf(t, 1e30f);
          h[i] = a * fast_rcp(d);
        }
        int ks = k >> 3;
#pragma unroll
        for (int ip = 0; ip < 4; ip++) {
          int slot = k * 36 + ((w4 + ip) ^ ks);
          *(float2*)(hT + slot * 2) = make_float2(h[2 * ip], h[2 * ip + 1]);
        }
      }
    }
    __syncwarp();

    // ---- GEMM2: logits = h @ W2, FFMA2 with duplicated-W smem chunks ----
    ull acc2[4][8];
#pragma unroll
    for (int ip = 0; ip < 4; ip++)
#pragma unroll
      for (int j = 0; j < 8; j++) acc2[ip][j] = 0ull;

    for (int c = 0; c < 8; c++) {
      int g = mm * 8 + c;
      int gn = g + 1;
      bool hasNext = (gn < 64);
      float4 pf[8];
      if (hasNext) {
        const float4* src = (const float4*)(W2 + gn * 8192);
#pragma unroll
        for (int q = 0; q < 8; q++) pf[q] = src[tid + q * 256];
      }

      const float* wch = w2dup + (g & 1) * 16384;
#pragma unroll 2
      for (int kk2 = 0; kk2 < 32; kk2++) {
        int k = c * 32 + kk2;
        const ulonglong2* wp = (const ulonglong2*)(wch + kk2 * 512 + l * 8);
        const ulonglong2* wq = (const ulonglong2*)(wch + kk2 * 512 + 256 + l * 8);
        ulonglong2 wA = wp[0];
        ulonglong2 wB = wp[1];
        ulonglong2 wC = wq[0];
        ulonglong2 wD = wq[1];
        int ks = k >> 3;
#pragma unroll
        for (int ip = 0; ip < 4; ip++) {
          int slot = k * 36 + ((w4 + ip) ^ ks);
          ull hv = *(const ull*)(hT + slot * 2);
          ffma2(acc2[ip][0], hv, wA.x);
          ffma2(acc2[ip][1], hv, wA.y);
          ffma2(acc2[ip][2], hv, wB.x);
          ffma2(acc2[ip][3], hv, wB.y);
          ffma2(acc2[ip][4], hv, wC.x);
          ffma2(acc2[ip][5], hv, wC.y);
          ffma2(acc2[ip][6], hv, wD.x);
          ffma2(acc2[ip][7], hv, wD.y);
        }
      }

      if (hasNext) {
        float* buf = w2dup + (gn & 1) * 16384;
#pragma unroll
        for (int q = 0; q < 8; q++) {
          int e = tid + q * 256;
          int k2 = e >> 6;
          int cc = (e & 63) * 4;
          float* dst = buf + k2 * 512 + cc * 2;
          float4 v = pf[q];
          *(float4*)(dst)     = make_float4(v.x, v.x, v.y, v.y);
          *(float4*)(dst + 4) = make_float4(v.z, v.z, v.w, v.w);
        }
      }
      __syncthreads();
    }

    // ---- per-row reductions (warp-level). lane cols: 4l..4l+3, 128+4l..+3
    float* wr = wred + w * 256;
    for (int i = 0; i < 8; i++) {
      int ip = i >> 1, hf = i & 1;
      int grow = row0 + w * 8 + i;
      float v[8];
#pragma unroll
      for (int j = 0; j < 8; j++) {
        float2 t = unpack2(acc2[ip][j]);
        int col = (j < 4) ? (l * 4 + j) : (128 + l * 4 + (j - 4));
        v[j] = (hf ? t.y : t.x) + b2s[col];
      }
      *(float4*)(wr + l * 4)       = make_float4(v[0], v[1], v[2], v[3]);
      *(float4*)(wr + 128 + l * 4) = make_float4(v[4], v[5], v[6], v[7]);

      float mx = v[0]; int ai = l * 4;
#pragma unroll
      for (int j = 1; j < 8; j++) {
        int col = (j < 4) ? (l * 4 + j) : (128 + l * 4 + (j - 4));
        if (v[j] > mx) { mx = v[j]; ai = col; }
      }
      for (int o = 16; o; o >>= 1) {
        float vm = __shfl_xor_sync(0xffffffffu, mx, o);
        int   vi = __shfl_xor_sync(0xffffffffu, ai, o);
        if (vm > mx || (vm == mx && vi < ai)) { mx = vm; ai = vi; }
      }
      float se = 0.f;
#pragma unroll
      for (int j = 0; j < 8; j++) se += __expf(v[j] - mx);
      for (int o = 16; o; o >>= 1)
        se += __shfl_xor_sync(0xffffffffu, se, o);
      float lse = mx + __logf(se);
      __syncwarp();

      if (pass == 0) {
        if (l == 0) {
          int tgt = g_target[grow * MG + mm];
          mapAcc += (double)(lse - wr[tgt]);
          hitAcc += (ai == tgt) ? 1u : 0u;
        }
      } else {
        int K = g_K[grow];
        const unsigned char* al = g_act + grow * NC;
        double gs = 0.0;
        for (int ci = l; ci < K; ci += 32)
          gs += (double)wr[g_ct[al[ci] * MG + mm]];
        for (int o = 16; o; o >>= 1)
          gs += __shfl_xor_sync(0xffffffffu, gs, o);
        if (l == 0) netAcc += (double)lse - gs / (double)K;
      }
      __syncwarp();
    }
  }

  if (l == 0) {
    if (pass == 0) {
      atomicAdd(&g_mapSum, mapAcc);
      atomicAdd(&g_hits, (unsigned long long)hitAcc);
    } else {
      atomicAdd(&g_netSum, netAcc);
    }
  }
}

// ---------------------------------------------------------------------------
// Kernel 5: finalize 5 scalars
// ---------------------------------------------------------------------------
__global__ void finalize_kernel(float* out) {
  if (threadIdx.x == 0) {
    double net = g_netSum / (double)NS;
    double map = g_mapSum / (double)NS;
    out[0] = (float)(net + map);
    out[1] = (float)net;
    out[2] = (float)map;
    out[3] = (float)((double)g_hits / ((double)NS * (double)MG));
    out[4] = (float)((double)g_hamSum / (double)g_actTot);
  }
}

// ---------------------------------------------------------------------------
extern "C" void kernel_launch(void* const* d_in, const int* in_sizes, int n_in,
                              void* d_out, int out_size) {
  const float* x    = (const float*)d_in[0];
  const int*   y    = (const int*)  d_in[1];
  const float* cen  = (const float*)d_in[2];
  const int*   perm = (const int*)  d_in[3];
  const void*  tmap = d_in[4];
  const void*  traw = d_in[5];
  const float* W1   = (const float*)d_in[6];
  const float* b1   = (const float*)d_in[7];
  const float* W2   = (const float*)d_in[8];
  const float* b2   = (const float*)d_in[9];
  float* out = (float*)d_out;

  uint32_t km0, km1, kr0, kr1;
  threefry2x32(0u, 1u, 0u, 0u, km0, km1);
  threefry2x32(0u, 1u, 0u, 1u, kr0, kr1);

  cudaFuncSetAttribute(mlp_kernel, cudaFuncAttributeMaxDynamicSharedMemorySize,
                       SM_FLOATS * 4);

  setup_kernel<<<1, 128>>>(cen, perm, (const unsigned char*)tmap,
                           (const unsigned char*)traw);
  prep_kernel<<<NS / 2, 256>>>(x, perm, tmap, traw, km0, km1, kr0, kr1);
  ham_kernel<<<NS / 8, 256>>>(y);
  dim3 grid(NS / 64, 2);
  mlp_kernel<<<grid, 256, SM_FLOATS * 4>>>(W1, b1, W2, b2);
  finalize_kernel<<<1, 32>>>(out);
  (void)in_sizes; (void)n_in; (void)out_size;
}

// round 6
// speedup vs baseline: 1.5890x; 1.5890x over previous
#include <cuda_runtime.h>
#include <cstdint>
#include <cstring>

#define NS    32768
#define NBITS 64
#define MG    8
#define HID   256
#define NC    100

typedef unsigned long long ull;

// ---------------------------------------------------------------------------
// Threefry-2x32, 20 rounds — bit-exact match of JAX's threefry2x32 primitive.
// ---------------------------------------------------------------------------
__host__ __device__ __forceinline__ void threefry2x32(
    uint32_t k0, uint32_t k1, uint32_t c0, uint32_t c1,
    uint32_t& o0, uint32_t& o1) {
  uint32_t ks2 = k0 ^ k1 ^ 0x1BD11BDAu;
  uint32_t x0 = c0 + k0;
  uint32_t x1 = c1 + k1;
#define TF_RND(r) { x0 += x1; x1 = (x1 << (r)) | (x1 >> (32 - (r))); x1 ^= x0; }
  TF_RND(13) TF_RND(15) TF_RND(26) TF_RND(6)
  x0 += k1;  x1 += ks2 + 1u;
  TF_RND(17) TF_RND(29) TF_RND(16) TF_RND(24)
  x0 += ks2; x1 += k0 + 2u;
  TF_RND(13) TF_RND(15) TF_RND(26) TF_RND(6)
  x0 += k0;  x1 += k1 + 3u;
  TF_RND(17) TF_RND(29) TF_RND(16) TF_RND(24)
  x0 += k1;  x1 += ks2 + 4u;
  TF_RND(13) TF_RND(15) TF_RND(26) TF_RND(6)
  x0 += ks2; x1 += k0 + 5u;
#undef TF_RND
  o0 = x0; o1 = x1;
}

// ---------------------------------------------------------------------------
// Device-global scratch
// ---------------------------------------------------------------------------
__device__ float g_xp  [NS * NBITS];
__device__ float g_xmap[NS * NBITS];
__device__ unsigned char g_target[NS * MG];
__device__ unsigned int  g_xbits[NS * 2];
__device__ int           g_K[NS];
__device__ unsigned char g_act[NS * NC];
__device__ unsigned char g_ct[NC * MG];
__device__ unsigned int  g_cbits[NC * 2];
__device__ double g_mapSum;
__device__ double g_netSum;
__device__ unsigned long long g_hits;
__device__ unsigned long long g_hamSum;
__device__ unsigned long long g_actTot;
__device__ int g_tmode;

__device__ __forceinline__ bool read_tpl(const void* p, int b) {
  if (g_tmode == 0) return ((const unsigned char*)p)[b] != 0;
  return ((const int*)p)[b] != 0;
}

// ---------------------------------------------------------------------------
// Kernel 1 (merged): accumulator init + template dtype detect + centroid prep
// ---------------------------------------------------------------------------
__global__ void setup_kernel(const float* __restrict__ cen,
                             const int* __restrict__ perm,
                             const unsigned char* tm, const unsigned char* tr) {
  __shared__ int permS[NBITS];
  int t = threadIdx.x;
  if (t < NBITS) permS[t] = perm[t];
  if (t == 0) {
    g_mapSum = 0.0; g_netSum = 0.0;
    g_hits = 0ull; g_hamSum = 0ull; g_actTot = 0ull;
    int has3F = 0, mis = 0;
    for (int i = 0; i < 64; i++) {
      unsigned char bm = tm[i], br = tr[i];
      if (bm == 0x3F || br == 0x3F) has3F = 1;
      if (i & 3) mis += (bm != 0) + (br != 0);
    }
    g_tmode = has3F ? 1 : (mis ? 0 : 1);
  }
  __syncthreads();
  if (t >= NC) return;
  unsigned int w0 = 0, w1 = 0;
  for (int b = 0; b < NBITS; b++) {
    bool bit = cen[t * NBITS + permS[b]] > 0.f;
    if (bit) { if (b < 32) w0 |= 1u << b; else w1 |= 1u << (b - 32); }
  }
  g_cbits[t * 2 + 0] = w0;
  g_cbits[t * 2 + 1] = w1;
  for (int m = 0; m < MG; m++) {
    unsigned int w = (m < 4) ? w0 : w1;
    g_ct[t * MG + m] = (unsigned char)((w >> ((m & 3) * 8)) & 0xffu);
  }
}

// ---------------------------------------------------------------------------
// Kernel 2: PRNG draws, stable argsort ranks, flips, targets, sign bits.
// ---------------------------------------------------------------------------
__global__ void prep_kernel(const float* __restrict__ x,
                            const int* __restrict__ perm,
                            const void* tmap, const void* traw,
                            uint32_t km0, uint32_t km1,
                            uint32_t kr0, uint32_t kr1) {
  __shared__ float xps[2][NBITS];
  __shared__ unsigned int us[2][2][NBITS];
  __shared__ int permS[NBITS];
  __shared__ int tposS[2][4];
  __shared__ int ranksS[2][2][4];
  __shared__ unsigned int rawb[2][2];
  __shared__ unsigned int xbw[2][2];

  int tid = threadIdx.x;
  if (tid < NBITS) permS[tid] = perm[tid];
  if (tid < 2) {
    const void* tp = (tid == 0) ? tmap : traw;
    int c = 0;
    for (int b = 0; b < NBITS; b++)
      if (read_tpl(tp, b)) { if (c < 4) tposS[tid][c] = b; c++; }
  }
  if (tid < 4) { rawb[tid >> 1][tid & 1] = 0u; xbw[tid >> 1][tid & 1] = 0u; }
  __syncthreads();

  int rid = tid >> 7;
  int sub = tid & 127;
  int op  = sub >> 6;
  int b   = sub & 63;
  int row = blockIdx.x * 2 + rid;

  if (op == 0) xps[rid][b] = x[row * NBITS + permS[b]];
  uint32_t k0 = op ? kr0 : km0;
  uint32_t k1 = op ? kr1 : km1;
  uint32_t o0, o1;
  threefry2x32(k0, k1, 0u, (uint32_t)(row * NBITS + b), o0, o1);
  us[rid][op][b] = (o0 ^ o1) >> 9;
  __syncthreads();

  if (b < 4) {
    int tpos = tposS[op][b];
    unsigned int ut = us[rid][op][tpos];
    int cnt = 0;
    for (int j = 0; j < NBITS; j++) {
      unsigned int uj = us[rid][op][j];
      cnt += (uj < ut) || (uj == ut && j < tpos);
    }
    ranksS[rid][op][b] = cnt;
  }
  __syncthreads();

  float v = xps[rid][b];
  bool flip = (b == ranksS[rid][op][0]) | (b == ranksS[rid][op][1]) |
              (b == ranksS[rid][op][2]) | (b == ranksS[rid][op][3]);
  if (op == 0) {
    g_xp  [row * NBITS + b] = v;
    g_xmap[row * NBITS + b] = flip ? -v : v;
    if (v > 0.f) atomicOr(&xbw[rid][b >> 5], 1u << (b & 31));
  } else {
    bool bit = flip ? (v < 0.f) : (v > 0.f);
    if (bit) atomicOr(&rawb[rid][b >> 5], 1u << (b & 31));
  }
  __syncthreads();

  if (op == 1 && b < MG) {
    unsigned int w = rawb[rid][b >> 2];
    g_target[row * MG + b] = (unsigned char)((w >> ((b & 3) * 8)) & 0xffu);
  }
  if (op == 0 && b < 2) g_xbits[row * 2 + b] = xbw[rid][b];
}

// ---------------------------------------------------------------------------
// Kernel 3: active-class compaction + exact hamming sums. 1 warp / row.
// ---------------------------------------------------------------------------
__global__ void ham_kernel(const int* __restrict__ y) {
  int tid = threadIdx.x, w = tid >> 5, l = tid & 31;
  int row = blockIdx.x * 8 + w;
  unsigned int xb0 = g_xbits[row * 2], xb1 = g_xbits[row * 2 + 1];
  int K = 0;
  unsigned long long hs = 0ull;
  for (int cb = 0; cb < 128; cb += 32) {
    int c = cb + l;
    bool act = (c < NC) && (y[row * NC + c] > 0);
    unsigned int msk = __ballot_sync(0xffffffffu, act);
    if (act) {
      int pos = K + __popc(msk & ((1u << l) - 1u));
      g_act[row * NC + pos] = (unsigned char)c;
      hs += (unsigned long long)(__popc(xb0 ^ g_cbits[c * 2]) +
                                 __popc(xb1 ^ g_cbits[c * 2 + 1]));
    }
    K += __popc(msk);
  }
  if (l == 0) g_K[row] = K;
  for (int o = 16; o; o >>= 1)
    hs += __shfl_xor_sync(0xffffffffu, hs, o);
  if (l == 0) {
    atomicAdd(&g_hamSum, hs);
    atomicAdd(&g_actTot, (unsigned long long)K);
  }
}

// ---------------------------------------------------------------------------
// Kernel 4: fused batched MLP + losses, FFMA2 with COLUMN-paired lanes.
//
// CTA: 256 thr = 8 warps; 64 rows; warp w owns rows [8w, 8w+8).
// Lane l owns cols [8l, 8l+8) = 4 f32x2 column pairs.
// W2 chunk in smem NATURAL layout [k][256] (32KB, cp.async double buffer):
//   lane reads ulonglong2 x2 -> 4 f32x2 W operands, zero movs, no duplication.
// hT [k][row] stride 66 floats: broadcast LDS64 gives rows (2i,2i+1);
//   dup each half into (h,h) with 1 mov -> reused across 4 col-pairs.
// acc2[i][jp]: f32x2 over col pair (8l+2jp, 8l+2jp+1), row 8w+i.
// ---------------------------------------------------------------------------
#define HSTRIDE  66
#define SM_W1S   0          // 2048 floats
#define SM_B1    2048       // 256
#define SM_B2    2304       // 256
#define SM_WRED  2560       // 2048
#define SM_HT    4608       // 16896 (256 k * 66)
#define SM_W2    21504      // 2 * 8192
#define SM_FLOATS 37888     // 151552 bytes

__device__ __forceinline__ void ffma2(ull& d, ull a, ull b) {
  asm("fma.rn.f32x2 %0, %1, %2, %0;" : "+l"(d) : "l"(a), "l"(b));
}
__device__ __forceinline__ ull dup2(float v) {
  ull r;
  asm("mov.b64 %0, {%1, %1};" : "=l"(r) : "f"(v));
  return r;
}
__device__ __forceinline__ float2 unpack2(ull v) {
  float2 t;
  asm("mov.b64 {%0, %1}, %2;" : "=f"(t.x), "=f"(t.y) : "l"(v));
  return t;
}
__device__ __forceinline__ void cpasync16(float* s, const float* g) {
  unsigned sa = (unsigned)__cvta_generic_to_shared(s);
  asm volatile("cp.async.cg.shared.global [%0], [%1], 16;" :: "r"(sa), "l"(g));
}
__device__ __forceinline__ float fast_rcp(float d) {
  float r = __uint_as_float(0x7EF311C3u - __float_as_uint(d));
  r = r * (2.0f - d * r);
  r = r * (2.0f - d * r);
  r = r * (2.0f - d * r);
  return r;
}

__global__ void __launch_bounds__(256)
mlp_kernel(const float* __restrict__ W1, const float* __restrict__ b1,
           const float* __restrict__ W2, const float* __restrict__ b2) {
  extern __shared__ float sm[];
  float* W1s  = sm + SM_W1S;
  float* b1s  = sm + SM_B1;
  float* b2s  = sm + SM_B2;
  float* wred = sm + SM_WRED;
  float* hT   = sm + SM_HT;
  float* w2s  = sm + SM_W2;

  int tid = threadIdx.x, w = tid >> 5, l = tid & 31;
  int pass = blockIdx.y;
  int row0 = blockIdx.x * 64;
  const float* inp = (pass == 0) ? g_xmap : g_xp;

  // x rows of this warp into registers: lane l holds cols (2l, 2l+1) x 8 rows
  float xperm[16];
#pragma unroll
  for (int r = 0; r < 8; r++) {
    float2 t = *(const float2*)(inp + (row0 + w * 8 + r) * NBITS + 2 * l);
    xperm[2 * r] = t.x; xperm[2 * r + 1] = t.y;
  }

  // prefetch chunk 0 of W2 (natural layout)
  {
#pragma unroll
    for (int q = 0; q < 8; q++)
      cpasync16(w2s + (tid + q * 256) * 4, W2 + (tid + q * 256) * 4);
    asm volatile("cp.async.commit_group;");
  }

  double mapAcc = 0.0, netAcc = 0.0;
  unsigned int hitAcc = 0;

  for (int mm = 0; mm < MG; mm++) {
    __syncthreads();
    {
      const float4* w1p = (const float4*)(W1 + mm * 2048);
      float4* w1d = (float4*)W1s;
      w1d[tid] = w1p[tid];
      w1d[tid + 256] = w1p[tid + 256];
      b1s[tid] = b1[mm * 256 + tid];
      b2s[tid] = b2[mm * 256 + tid];
    }
    __syncthreads();

    // ---- GEMM1: h = silu(xs @ W1 + b1) -> hT[k][row], stride 66 ----
    {
      float xv[8][8];
#pragma unroll
      for (int i = 0; i < 8; i++)
#pragma unroll
        for (int s = 0; s < 8; s++)
          xv[i][s] = __shfl_sync(0xffffffffu, xperm[2 * i + (s & 1)],
                                 mm * 4 + (s >> 1));
#pragma unroll
      for (int kk = 0; kk < 8; kk++) {
        int k = kk * 32 + l;
        float w1c[8];
#pragma unroll
        for (int s = 0; s < 8; s++) w1c[s] = W1s[s * 256 + k];
        float bk = b1s[k];
        float* hp = hT + k * HSTRIDE + 8 * w;
#pragma unroll
        for (int ip = 0; ip < 4; ip++) {
          float h2[2];
#pragma unroll
          for (int u = 0; u < 2; u++) {
            int i = 2 * ip + u;
            float a = bk;
#pragma unroll
            for (int s = 0; s < 8; s++) a = fmaf(xv[i][s], w1c[s], a);
            float t = __expf(-a);
            float d = 1.0f + fminf(t, 1e30f);
            h2[u] = a * fast_rcp(d);
          }
          *(float2*)(hp + 2 * ip) = make_float2(h2[0], h2[1]);
        }
      }
    }
    __syncwarp();

    // ---- GEMM2: logits = h @ W2, FFMA2, column-paired ----
    ull acc2[8][4];
#pragma unroll
    for (int i = 0; i < 8; i++)
#pragma unroll
      for (int j = 0; j < 4; j++) acc2[i][j] = 0ull;

    for (int c = 0; c < 8; c++) {
      int g = mm * 8 + c;
      if (g + 1 < 64) {
        const float* src = W2 + (g + 1) * 8192;
        float* dst = w2s + ((g + 1) & 1) * 8192;
#pragma unroll
        for (int q = 0; q < 8; q++)
          cpasync16(dst + (tid + q * 256) * 4, src + (tid + q * 256) * 4);
        asm volatile("cp.async.commit_group;");
        asm volatile("cp.async.wait_group 1;");
      } else {
        asm volatile("cp.async.wait_group 0;");
      }
      __syncthreads();

      const float* wch = w2s + (g & 1) * 8192 + 8 * l;
      const float* hb  = hT + (c * 32) * HSTRIDE + 8 * w;
#pragma unroll 2
      for (int kk2 = 0; kk2 < 32; kk2++) {
        ulonglong2 wp = *(const ulonglong2*)(wch + kk2 * 256);
        ulonglong2 wq = *(const ulonglong2*)(wch + kk2 * 256 + 4);
        const float* hk = hb + kk2 * HSTRIDE;
#pragma unroll
        for (int ip = 0; ip < 4; ip++) {
          float2 hpair = *(const float2*)(hk + 2 * ip);
          ull h0 = dup2(hpair.x);
          ull h1 = dup2(hpair.y);
          ffma2(acc2[2 * ip][0],     h0, wp.x);
          ffma2(acc2[2 * ip][1],     h0, wp.y);
          ffma2(acc2[2 * ip][2],     h0, wq.x);
          ffma2(acc2[2 * ip][3],     h0, wq.y);
          ffma2(acc2[2 * ip + 1][0], h1, wp.x);
          ffma2(acc2[2 * ip + 1][1], h1, wp.y);
          ffma2(acc2[2 * ip + 1][2], h1, wq.x);
          ffma2(acc2[2 * ip + 1][3], h1, wq.y);
        }
      }
      __syncthreads();
    }

    // ---- per-row reductions (warp-level). lane cols: 8l..8l+7 ----
    float* wr = wred + w * 256;
    float2 bb[4];
#pragma unroll
    for (int j = 0; j < 4; j++)
      bb[j] = *(const float2*)(b2s + 8 * l + 2 * j);

    for (int i = 0; i < 8; i++) {
      int grow = row0 + w * 8 + i;
      float v[8];
#pragma unroll
      for (int j = 0; j < 4; j++) {
        float2 t = unpack2(acc2[i][j]);
        v[2 * j]     = t.x + bb[j].x;
        v[2 * j + 1] = t.y + bb[j].y;
      }
      *(float4*)(wr + 8 * l)     = make_float4(v[0], v[1], v[2], v[3]);
      *(float4*)(wr + 8 * l + 4) = make_float4(v[4], v[5], v[6], v[7]);

      float mx = v[0]; int ai = 8 * l;
#pragma unroll
      for (int j = 1; j < 8; j++)
        if (v[j] > mx) { mx = v[j]; ai = 8 * l + j; }
      for (int o = 16; o; o >>= 1) {
        float vm = __shfl_xor_sync(0xffffffffu, mx, o);
        int   vi = __shfl_xor_sync(0xffffffffu, ai, o);
        if (vm > mx || (vm == mx && vi < ai)) { mx = vm; ai = vi; }
      }
      float se = 0.f;
#pragma unroll
      for (int j = 0; j < 8; j++) se += __expf(v[j] - mx);
      for (int o = 16; o; o >>= 1)
        se += __shfl_xor_sync(0xffffffffu, se, o);
      float lse = mx + __logf(se);
      __syncwarp();

      if (pass == 0) {
        if (l == 0) {
          int tgt = g_target[grow * MG + mm];
          mapAcc += (double)(lse - wr[tgt]);
          hitAcc += (ai == tgt) ? 1u : 0u;
        }
      } else {
        int K = g_K[grow];
        const unsigned char* al = g_act + grow * NC;
        double gs = 0.0;
        for (int ci = l; ci < K; ci += 32)
          gs += (double)wr[g_ct[al[ci] * MG + mm]];
        for (int o = 16; o; o >>= 1)
          gs += __shfl_xor_sync(0xffffffffu, gs, o);
        if (l == 0) netAcc += (double)lse - gs / (double)K;
      }
      __syncwarp();
    }
  }

  if (l == 0) {
    if (pass == 0) {
      atomicAdd(&g_mapSum, mapAcc);
      atomicAdd(&g_hits, (unsigned long long)hitAcc);
    } else {
      atomicAdd(&g_netSum, netAcc);
    }
  }
}

// ---------------------------------------------------------------------------
// Kernel 5: finalize 5 scalars
// ---------------------------------------------------------------------------
__global__ void finalize_kernel(float* out) {
  if (threadIdx.x == 0) {
    double net = g_netSum / (double)NS;
    double map = g_mapSum / (double)NS;
    out[0] = (float)(net + map);
    out[1] = (float)net;
    out[2] = (float)map;
    out[3] = (float)((double)g_hits / ((double)NS * (double)MG));
    out[4] = (float)((double)g_hamSum / (double)g_actTot);
  }
}

// ---------------------------------------------------------------------------
extern "C" void kernel_launch(void* const* d_in, const int* in_sizes, int n_in,
                              void* d_out, int out_size) {
  const float* x    = (const float*)d_in[0];
  const int*   y    = (const int*)  d_in[1];
  const float* cen  = (const float*)d_in[2];
  const int*   perm = (const int*)  d_in[3];
  const void*  tmap = d_in[4];
  const void*  traw = d_in[5];
  const float* W1   = (const float*)d_in[6];
  const float* b1   = (const float*)d_in[7];
  const float* W2   = (const float*)d_in[8];
  const float* b2   = (const float*)d_in[9];
  float* out = (float*)d_out;

  uint32_t km0, km1, kr0, kr1;
  threefry2x32(0u, 1u, 0u, 0u, km0, km1);
  threefry2x32(0u, 1u, 0u, 1u, kr0, kr1);

  cudaFuncSetAttribute(mlp_kernel, cudaFuncAttributeMaxDynamicSharedMemorySize,
                       SM_FLOATS * 4);

  setup_kernel<<<1, 128>>>(cen, perm, (const unsigned char*)tmap,
                           (const unsigned char*)traw);
  prep_kernel<<<NS / 2, 256>>>(x, perm, tmap, traw, km0, km1, kr0, kr1);
  ham_kernel<<<NS / 8, 256>>>(y);
  dim3 grid(NS / 64, 2);
  mlp_kernel<<<grid, 256, SM_FLOATS * 4>>>(W1, b1, W2, b2);
  finalize_kernel<<<1, 32>>>(out);
  (void)in_sizes; (void)n_in; (void)out_size;
}

// round 7
// speedup vs baseline: 1.9198x; 1.2082x over previous
#include <cuda_runtime.h>
#include <cstdint>
#include <cstring>

#define NS    32768
#define NBITS 64
#define MG    8
#define HID   256
#define NC    100

typedef unsigned long long ull;

// ---------------------------------------------------------------------------
// Threefry-2x32, 20 rounds — bit-exact match of JAX's threefry2x32 primitive.
// ---------------------------------------------------------------------------
__host__ __device__ __forceinline__ void threefry2x32(
    uint32_t k0, uint32_t k1, uint32_t c0, uint32_t c1,
    uint32_t& o0, uint32_t& o1) {
  uint32_t ks2 = k0 ^ k1 ^ 0x1BD11BDAu;
  uint32_t x0 = c0 + k0;
  uint32_t x1 = c1 + k1;
#define TF_RND(r) { x0 += x1; x1 = (x1 << (r)) | (x1 >> (32 - (r))); x1 ^= x0; }
  TF_RND(13) TF_RND(15) TF_RND(26) TF_RND(6)
  x0 += k1;  x1 += ks2 + 1u;
  TF_RND(17) TF_RND(29) TF_RND(16) TF_RND(24)
  x0 += ks2; x1 += k0 + 2u;
  TF_RND(13) TF_RND(15) TF_RND(26) TF_RND(6)
  x0 += k0;  x1 += k1 + 3u;
  TF_RND(17) TF_RND(29) TF_RND(16) TF_RND(24)
  x0 += k1;  x1 += ks2 + 4u;
  TF_RND(13) TF_RND(15) TF_RND(26) TF_RND(6)
  x0 += ks2; x1 += k0 + 5u;
#undef TF_RND
  o0 = x0; o1 = x1;
}

// ---------------------------------------------------------------------------
// Device-global scratch
// ---------------------------------------------------------------------------
__device__ float g_xp  [NS * NBITS];
__device__ float g_xmap[NS * NBITS];
__device__ unsigned char g_target[NS * MG];
__device__ unsigned int  g_xbits[NS * 2];
__device__ int           g_K[NS];
__device__ unsigned char g_act[NS * NC];
__device__ unsigned char g_ct[NC * MG];
__device__ unsigned int  g_cbits[NC * 2];
__device__ double g_mapSum;
__device__ double g_netSum;
__device__ unsigned long long g_hits;
__device__ unsigned long long g_hamSum;
__device__ unsigned long long g_actTot;
__device__ int g_tmode;

__device__ __forceinline__ bool read_tpl(const void* p, int b) {
  if (g_tmode == 0) return ((const unsigned char*)p)[b] != 0;
  return ((const int*)p)[b] != 0;
}

// ---------------------------------------------------------------------------
// Kernel 1 (merged): accumulator init + template dtype detect + centroid prep
// ---------------------------------------------------------------------------
__global__ void setup_kernel(const float* __restrict__ cen,
                             const int* __restrict__ perm,
                             const unsigned char* tm, const unsigned char* tr) {
  __shared__ int permS[NBITS];
  int t = threadIdx.x;
  if (t < NBITS) permS[t] = perm[t];
  if (t == 0) {
    g_mapSum = 0.0; g_netSum = 0.0;
    g_hits = 0ull; g_hamSum = 0ull; g_actTot = 0ull;
    int has3F = 0, mis = 0;
    for (int i = 0; i < 64; i++) {
      unsigned char bm = tm[i], br = tr[i];
      if (bm == 0x3F || br == 0x3F) has3F = 1;
      if (i & 3) mis += (bm != 0) + (br != 0);
    }
    g_tmode = has3F ? 1 : (mis ? 0 : 1);
  }
  __syncthreads();
  if (t >= NC) return;
  unsigned int w0 = 0, w1 = 0;
  for (int b = 0; b < NBITS; b++) {
    bool bit = cen[t * NBITS + permS[b]] > 0.f;
    if (bit) { if (b < 32) w0 |= 1u << b; else w1 |= 1u << (b - 32); }
  }
  g_cbits[t * 2 + 0] = w0;
  g_cbits[t * 2 + 1] = w1;
  for (int m = 0; m < MG; m++) {
    unsigned int w = (m < 4) ? w0 : w1;
    g_ct[t * MG + m] = (unsigned char)((w >> ((m & 3) * 8)) & 0xffu);
  }
}

// ---------------------------------------------------------------------------
// Kernel 2: PRNG draws, stable argsort ranks, flips, targets, sign bits.
// ---------------------------------------------------------------------------
__global__ void prep_kernel(const float* __restrict__ x,
                            const int* __restrict__ perm,
                            const void* tmap, const void* traw,
                            uint32_t km0, uint32_t km1,
                            uint32_t kr0, uint32_t kr1) {
  __shared__ float xps[2][NBITS];
  __shared__ unsigned int us[2][2][NBITS];
  __shared__ int permS[NBITS];
  __shared__ int tposS[2][4];
  __shared__ int ranksS[2][2][4];
  __shared__ unsigned int rawb[2][2];
  __shared__ unsigned int xbw[2][2];

  int tid = threadIdx.x;
  if (tid < NBITS) permS[tid] = perm[tid];
  if (tid < 2) {
    const void* tp = (tid == 0) ? tmap : traw;
    int c = 0;
    for (int b = 0; b < NBITS; b++)
      if (read_tpl(tp, b)) { if (c < 4) tposS[tid][c] = b; c++; }
  }
  if (tid < 4) { rawb[tid >> 1][tid & 1] = 0u; xbw[tid >> 1][tid & 1] = 0u; }
  __syncthreads();

  int rid = tid >> 7;
  int sub = tid & 127;
  int op  = sub >> 6;
  int b   = sub & 63;
  int row = blockIdx.x * 2 + rid;

  if (op == 0) xps[rid][b] = x[row * NBITS + permS[b]];
  uint32_t k0 = op ? kr0 : km0;
  uint32_t k1 = op ? kr1 : km1;
  uint32_t o0, o1;
  threefry2x32(k0, k1, 0u, (uint32_t)(row * NBITS + b), o0, o1);
  us[rid][op][b] = (o0 ^ o1) >> 9;
  __syncthreads();

  if (b < 4) {
    int tpos = tposS[op][b];
    unsigned int ut = us[rid][op][tpos];
    int cnt = 0;
    for (int j = 0; j < NBITS; j++) {
      unsigned int uj = us[rid][op][j];
      cnt += (uj < ut) || (uj == ut && j < tpos);
    }
    ranksS[rid][op][b] = cnt;
  }
  __syncthreads();

  float v = xps[rid][b];
  bool flip = (b == ranksS[rid][op][0]) | (b == ranksS[rid][op][1]) |
              (b == ranksS[rid][op][2]) | (b == ranksS[rid][op][3]);
  if (op == 0) {
    g_xp  [row * NBITS + b] = v;
    g_xmap[row * NBITS + b] = flip ? -v : v;
    if (v > 0.f) atomicOr(&xbw[rid][b >> 5], 1u << (b & 31));
  } else {
    bool bit = flip ? (v < 0.f) : (v > 0.f);
    if (bit) atomicOr(&rawb[rid][b >> 5], 1u << (b & 31));
  }
  __syncthreads();

  if (op == 1 && b < MG) {
    unsigned int w = rawb[rid][b >> 2];
    g_target[row * MG + b] = (unsigned char)((w >> ((b & 3) * 8)) & 0xffu);
  }
  if (op == 0 && b < 2) g_xbits[row * 2 + b] = xbw[rid][b];
}

// ---------------------------------------------------------------------------
// Kernel 3: active-class compaction + exact hamming sums. 1 warp / row.
// ---------------------------------------------------------------------------
__global__ void ham_kernel(const int* __restrict__ y) {
  int tid = threadIdx.x, w = tid >> 5, l = tid & 31;
  int row = blockIdx.x * 8 + w;
  unsigned int xb0 = g_xbits[row * 2], xb1 = g_xbits[row * 2 + 1];
  int K = 0;
  unsigned long long hs = 0ull;
  for (int cb = 0; cb < 128; cb += 32) {
    int c = cb + l;
    bool act = (c < NC) && (y[row * NC + c] > 0);
    unsigned int msk = __ballot_sync(0xffffffffu, act);
    if (act) {
      int pos = K + __popc(msk & ((1u << l) - 1u));
      g_act[row * NC + pos] = (unsigned char)c;
      hs += (unsigned long long)(__popc(xb0 ^ g_cbits[c * 2]) +
                                 __popc(xb1 ^ g_cbits[c * 2 + 1]));
    }
    K += __popc(msk);
  }
  if (l == 0) g_K[row] = K;
  for (int o = 16; o; o >>= 1)
    hs += __shfl_xor_sync(0xffffffffu, hs, o);
  if (l == 0) {
    atomicAdd(&g_hamSum, hs);
    atomicAdd(&g_actTot, (unsigned long long)K);
  }
}

// ---------------------------------------------------------------------------
// Kernel 4: fused batched MLP + losses. FFMA2, conflict-free W LDS, 2 CTAs/SM.
//
// CTA: 256 thr = 8 warps; 64 rows; warp w owns rows [8w, 8w+8).
// Lane l owns cols {4l..4l+3} U {128+4l..+3}: both W LDS128 land on 8
//   distinct bank quads per phase -> conflict-free (4 cyc each).
// W2 staged as 16KB half-chunks (16 k x 256 cols), 2-deep cp.async ring.
// hT [k][row] stride 66: broadcast LDS64 row-pairs, dup into f32x2.
// wred aliases W1s (disjoint lifetimes). smem = 108KB -> 2 CTAs/SM.
// ---------------------------------------------------------------------------
#define HSTRIDE  66
#define SM_W1S   0          // 2048 floats (doubles as wred)
#define SM_B1    2048       // 256
#define SM_B2    2304       // 256
#define SM_HT    2560       // 16896 (256 k * 66)
#define SM_W2    19456      // 2 * 4096 (16KB half-chunks)
#define SM_FLOATS 27648     // 110592 bytes

__device__ __forceinline__ void ffma2(ull& d, ull a, ull b) {
  asm("fma.rn.f32x2 %0, %1, %2, %0;" : "+l"(d) : "l"(a), "l"(b));
}
__device__ __forceinline__ ull dup2(float v) {
  ull r;
  asm("mov.b64 %0, {%1, %1};" : "=l"(r) : "f"(v));
  return r;
}
__device__ __forceinline__ float2 unpack2(ull v) {
  float2 t;
  asm("mov.b64 {%0, %1}, %2;" : "=f"(t.x), "=f"(t.y) : "l"(v));
  return t;
}
__device__ __forceinline__ void cpasync16(float* s, const float* g) {
  unsigned sa = (unsigned)__cvta_generic_to_shared(s);
  asm volatile("cp.async.cg.shared.global [%0], [%1], 16;" :: "r"(sa), "l"(g));
}
__device__ __forceinline__ float fast_rcp(float d) {
  float r = __uint_as_float(0x7EF311C3u - __float_as_uint(d));
  r = r * (2.0f - d * r);
  r = r * (2.0f - d * r);
  r = r * (2.0f - d * r);
  return r;
}

__global__ void __launch_bounds__(256, 2)
mlp_kernel(const float* __restrict__ W1, const float* __restrict__ b1,
           const float* __restrict__ W2, const float* __restrict__ b2) {
  extern __shared__ float sm[];
  float* W1s  = sm + SM_W1S;
  float* b1s  = sm + SM_B1;
  float* b2s  = sm + SM_B2;
  float* wred = sm + SM_W1S;   // alias: W1s dead after GEMM1, wred after GEMM2
  float* hT   = sm + SM_HT;
  float* w2s  = sm + SM_W2;

  int tid = threadIdx.x, w = tid >> 5, l = tid & 31;
  int pass = blockIdx.y;
  int row0 = blockIdx.x * 64;
  const float* inp = (pass == 0) ? g_xmap : g_xp;

  // x rows of this warp into registers: lane l holds cols (2l, 2l+1) x 8 rows
  float xperm[16];
#pragma unroll
  for (int r = 0; r < 8; r++) {
    float2 t = *(const float2*)(inp + (row0 + w * 8 + r) * NBITS + 2 * l);
    xperm[2 * r] = t.x; xperm[2 * r + 1] = t.y;
  }

  // prefetch half-chunk 0 of W2 (16 k x 256 cols = 4096 floats)
  {
#pragma unroll
    for (int q = 0; q < 4; q++)
      cpasync16(w2s + (tid + q * 256) * 4, W2 + (tid + q * 256) * 4);
    asm volatile("cp.async.commit_group;");
  }

  double mapAcc = 0.0, netAcc = 0.0;
  unsigned int hitAcc = 0;

  for (int mm = 0; mm < MG; mm++) {
    __syncthreads();
    {
      const float4* w1p = (const float4*)(W1 + mm * 2048);
      float4* w1d = (float4*)W1s;
      w1d[tid] = w1p[tid];
      w1d[tid + 256] = w1p[tid + 256];
      b1s[tid] = b1[mm * 256 + tid];
      b2s[tid] = b2[mm * 256 + tid];
    }
    __syncthreads();

    // ---- GEMM1: h = silu(xs @ W1 + b1) -> hT[k][row], stride 66 ----
    {
      float xv[8][8];
#pragma unroll
      for (int i = 0; i < 8; i++)
#pragma unroll
        for (int s = 0; s < 8; s++)
          xv[i][s] = __shfl_sync(0xffffffffu, xperm[2 * i + (s & 1)],
                                 mm * 4 + (s >> 1));
#pragma unroll
      for (int kk = 0; kk < 8; kk++) {
        int k = kk * 32 + l;
        float w1c[8];
#pragma unroll
        for (int s = 0; s < 8; s++) w1c[s] = W1s[s * 256 + k];
        float bk = b1s[k];
        float* hp = hT + k * HSTRIDE + 8 * w;
#pragma unroll
        for (int ip = 0; ip < 4; ip++) {
          float h2[2];
#pragma unroll
          for (int u = 0; u < 2; u++) {
            int i = 2 * ip + u;
            float a = bk;
#pragma unroll
            for (int s = 0; s < 8; s++) a = fmaf(xv[i][s], w1c[s], a);
            float t = __expf(-a);
            float d = 1.0f + fminf(t, 1e30f);
            h2[u] = a * fast_rcp(d);
          }
          *(float2*)(hp + 2 * ip) = make_float2(h2[0], h2[1]);
        }
      }
    }
    __syncwarp();

    // ---- GEMM2: logits = h @ W2, FFMA2, 16-k half-chunks ----
    ull acc2[8][4];
#pragma unroll
    for (int i = 0; i < 8; i++)
#pragma unroll
      for (int j = 0; j < 4; j++) acc2[i][j] = 0ull;

    for (int hc = 0; hc < 16; hc++) {
      int g2 = mm * 16 + hc;
      if (g2 + 1 < 128) {
        const float* src = W2 + (g2 + 1) * 4096;
        float* dst = w2s + ((g2 + 1) & 1) * 4096;
#pragma unroll
        for (int q = 0; q < 4; q++)
          cpasync16(dst + (tid + q * 256) * 4, src + (tid + q * 256) * 4);
        asm volatile("cp.async.commit_group;");
        asm volatile("cp.async.wait_group 1;");
      } else {
        asm volatile("cp.async.wait_group 0;");
      }
      __syncthreads();

      const float* wch = w2s + (g2 & 1) * 4096 + 4 * l;
      const float* hb  = hT + (hc * 16) * HSTRIDE + 8 * w;
#pragma unroll 2
      for (int kk2 = 0; kk2 < 16; kk2++) {
        ulonglong2 wp = *(const ulonglong2*)(wch + kk2 * 256);
        ulonglong2 wq = *(const ulonglong2*)(wch + kk2 * 256 + 128);
        const float* hk = hb + kk2 * HSTRIDE;
#pragma unroll
        for (int ip = 0; ip < 4; ip++) {
          float2 hpair = *(const float2*)(hk + 2 * ip);
          ull h0 = dup2(hpair.x);
          ull h1 = dup2(hpair.y);
          ffma2(acc2[2 * ip][0],     h0, wp.x);
          ffma2(acc2[2 * ip][1],     h0, wp.y);
          ffma2(acc2[2 * ip][2],     h0, wq.x);
          ffma2(acc2[2 * ip][3],     h0, wq.y);
          ffma2(acc2[2 * ip + 1][0], h1, wp.x);
          ffma2(acc2[2 * ip + 1][1], h1, wp.y);
          ffma2(acc2[2 * ip + 1][2], h1, wq.x);
          ffma2(acc2[2 * ip + 1][3], h1, wq.y);
        }
      }
      __syncthreads();
    }

    // ---- per-row reductions. lane cols: 4l..4l+3, 128+4l..128+4l+3 ----
    float* wr = wred + w * 256;
    float4 bA = *(const float4*)(b2s + 4 * l);
    float4 bB = *(const float4*)(b2s + 128 + 4 * l);

    for (int i = 0; i < 8; i++) {
      int grow = row0 + w * 8 + i;
      float v[8];
      {
        float2 t0 = unpack2(acc2[i][0]);
        float2 t1 = unpack2(acc2[i][1]);
        float2 t2 = unpack2(acc2[i][2]);
        float2 t3 = unpack2(acc2[i][3]);
        v[0] = t0.x + bA.x; v[1] = t0.y + bA.y;
        v[2] = t1.x + bA.z; v[3] = t1.y + bA.w;
        v[4] = t2.x + bB.x; v[5] = t2.y + bB.y;
        v[6] = t3.x + bB.z; v[7] = t3.y + bB.w;
      }
      *(float4*)(wr + 4 * l)       = make_float4(v[0], v[1], v[2], v[3]);
      *(float4*)(wr + 128 + 4 * l) = make_float4(v[4], v[5], v[6], v[7]);

      float mx = v[0]; int ai = 4 * l;
#pragma unroll
      for (int j = 1; j < 8; j++) {
        int col = (j < 4) ? (4 * l + j) : (128 + 4 * l + (j - 4));
        if (v[j] > mx) { mx = v[j]; ai = col; }
      }
      for (int o = 16; o; o >>= 1) {
        float vm = __shfl_xor_sync(0xffffffffu, mx, o);
        int   vi = __shfl_xor_sync(0xffffffffu, ai, o);
        if (vm > mx || (vm == mx && vi < ai)) { mx = vm; ai = vi; }
      }
      float se = 0.f;
#pragma unroll
      for (int j = 0; j < 8; j++) se += __expf(v[j] - mx);
      for (int o = 16; o; o >>= 1)
        se += __shfl_xor_sync(0xffffffffu, se, o);
      float lse = mx + __logf(se);
      __syncwarp();

      if (pass == 0) {
        if (l == 0) {
          int tgt = g_target[grow * MG + mm];
          mapAcc += (double)(lse - wr[tgt]);
          hitAcc += (ai == tgt) ? 1u : 0u;
        }
      } else {
        int K = g_K[grow];
        const unsigned char* al = g_act + grow * NC;
        double gs = 0.0;
        for (int ci = l; ci < K; ci += 32)
          gs += (double)wr[g_ct[al[ci] * MG + mm]];
        for (int o = 16; o; o >>= 1)
          gs += __shfl_xor_sync(0xffffffffu, gs, o);
        if (l == 0) netAcc += (double)lse - gs / (double)K;
      }
      __syncwarp();
    }
  }

  if (l == 0) {
    if (pass == 0) {
      atomicAdd(&g_mapSum, mapAcc);
      atomicAdd(&g_hits, (unsigned long long)hitAcc);
    } else {
      atomicAdd(&g_netSum, netAcc);
    }
  }
}

// ---------------------------------------------------------------------------
// Kernel 5: finalize 5 scalars
// ---------------------------------------------------------------------------
__global__ void finalize_kernel(float* out) {
  if (threadIdx.x == 0) {
    double net = g_netSum / (double)NS;
    double map = g_mapSum / (double)NS;
    out[0] = (float)(net + map);
    out[1] = (float)net;
    out[2] = (float)map;
    out[3] = (float)((double)g_hits / ((double)NS * (double)MG));
    out[4] = (float)((double)g_hamSum / (double)g_actTot);
  }
}

// ---------------------------------------------------------------------------
extern "C" void kernel_launch(void* const* d_in, const int* in_sizes, int n_in,
                              void* d_out, int out_size) {
  const float* x    = (const float*)d_in[0];
  const int*   y    = (const int*)  d_in[1];
  const float* cen  = (const float*)d_in[2];
  const int*   perm = (const int*)  d_in[3];
  const void*  tmap = d_in[4];
  const void*  traw = d_in[5];
  const float* W1   = (const float*)d_in[6];
  const float* b1   = (const float*)d_in[7];
  const float* W2   = (const float*)d_in[8];
  const float* b2   = (const float*)d_in[9];
  float* out = (float*)d_out;

  uint32_t km0, km1, kr0, kr1;
  threefry2x32(0u, 1u, 0u, 0u, km0, km1);
  threefry2x32(0u, 1u, 0u, 1u, kr0, kr1);

  cudaFuncSetAttribute(mlp_kernel, cudaFuncAttributeMaxDynamicSharedMemorySize,
                       SM_FLOATS * 4);

  setup_kernel<<<1, 128>>>(cen, perm, (const unsigned char*)tmap,
                           (const unsigned char*)traw);
  prep_kernel<<<NS / 2, 256>>>(x, perm, tmap, traw, km0, km1, kr0, kr1);
  ham_kernel<<<NS / 8, 256>>>(y);
  dim3 grid(NS / 64, 2);
  mlp_kernel<<<grid, 256, SM_FLOATS * 4>>>(W1, b1, W2, b2);
  finalize_kernel<<<1, 32>>>(out);
  (void)in_sizes; (void)n_in; (void)out_size;
}

// round 8
// speedup vs baseline: 1.9727x; 1.0276x over previous
#include <cuda_runtime.h>
#include <cstdint>
#include <cstring>

#define NS    32768
#define NBITS 64
#define MG    8
#define HID   256
#define NC    100

typedef unsigned long long ull;

// ---------------------------------------------------------------------------
// Threefry-2x32, 20 rounds — bit-exact match of JAX's threefry2x32 primitive.
// ---------------------------------------------------------------------------
__host__ __device__ __forceinline__ void threefry2x32(
    uint32_t k0, uint32_t k1, uint32_t c0, uint32_t c1,
    uint32_t& o0, uint32_t& o1) {
  uint32_t ks2 = k0 ^ k1 ^ 0x1BD11BDAu;
  uint32_t x0 = c0 + k0;
  uint32_t x1 = c1 + k1;
#define TF_RND(r) { x0 += x1; x1 = (x1 << (r)) | (x1 >> (32 - (r))); x1 ^= x0; }
  TF_RND(13) TF_RND(15) TF_RND(26) TF_RND(6)
  x0 += k1;  x1 += ks2 + 1u;
  TF_RND(17) TF_RND(29) TF_RND(16) TF_RND(24)
  x0 += ks2; x1 += k0 + 2u;
  TF_RND(13) TF_RND(15) TF_RND(26) TF_RND(6)
  x0 += k0;  x1 += k1 + 3u;
  TF_RND(17) TF_RND(29) TF_RND(16) TF_RND(24)
  x0 += k1;  x1 += ks2 + 4u;
  TF_RND(13) TF_RND(15) TF_RND(26) TF_RND(6)
  x0 += ks2; x1 += k0 + 5u;
#undef TF_RND
  o0 = x0; o1 = x1;
}

// ---------------------------------------------------------------------------
// Device-global scratch
// ---------------------------------------------------------------------------
__device__ float g_xp  [NS * NBITS];
__device__ float g_xmap[NS * NBITS];
__device__ unsigned char g_target[NS * MG];
__device__ unsigned int  g_xbits[NS * 2];
__device__ int           g_K[NS];
__device__ unsigned char g_act[NS * NC];
__device__ unsigned char g_ct[NC * MG];
__device__ unsigned int  g_cbits[NC * 2];
__device__ double g_mapSum;
__device__ double g_netSum;
__device__ unsigned long long g_hits;
__device__ unsigned long long g_hamSum;
__device__ unsigned long long g_actTot;
__device__ int g_tmode;

__device__ __forceinline__ bool read_tpl(const void* p, int b) {
  if (g_tmode == 0) return ((const unsigned char*)p)[b] != 0;
  return ((const int*)p)[b] != 0;
}

// ---------------------------------------------------------------------------
// Kernel 1 (merged): accumulator init + template dtype detect + centroid prep
// ---------------------------------------------------------------------------
__global__ void setup_kernel(const float* __restrict__ cen,
                             const int* __restrict__ perm,
                             const unsigned char* tm, const unsigned char* tr) {
  __shared__ int permS[NBITS];
  int t = threadIdx.x;
  if (t < NBITS) permS[t] = perm[t];
  if (t == 0) {
    g_mapSum = 0.0; g_netSum = 0.0;
    g_hits = 0ull; g_hamSum = 0ull; g_actTot = 0ull;
    int has3F = 0, mis = 0;
    for (int i = 0; i < 64; i++) {
      unsigned char bm = tm[i], br = tr[i];
      if (bm == 0x3F || br == 0x3F) has3F = 1;
      if (i & 3) mis += (bm != 0) + (br != 0);
    }
    g_tmode = has3F ? 1 : (mis ? 0 : 1);
  }
  __syncthreads();
  if (t >= NC) return;
  unsigned int w0 = 0, w1 = 0;
  for (int b = 0; b < NBITS; b++) {
    bool bit = cen[t * NBITS + permS[b]] > 0.f;
    if (bit) { if (b < 32) w0 |= 1u << b; else w1 |= 1u << (b - 32); }
  }
  g_cbits[t * 2 + 0] = w0;
  g_cbits[t * 2 + 1] = w1;
  for (int m = 0; m < MG; m++) {
    unsigned int w = (m < 4) ? w0 : w1;
    g_ct[t * MG + m] = (unsigned char)((w >> ((m & 3) * 8)) & 0xffu);
  }
}

// ---------------------------------------------------------------------------
// Kernel 2: PRNG draws, stable argsort ranks, flips, targets, sign bits.
// ---------------------------------------------------------------------------
__global__ void prep_kernel(const float* __restrict__ x,
                            const int* __restrict__ perm,
                            const void* tmap, const void* traw,
                            uint32_t km0, uint32_t km1,
                            uint32_t kr0, uint32_t kr1) {
  __shared__ float xps[2][NBITS];
  __shared__ unsigned int us[2][2][NBITS];
  __shared__ int permS[NBITS];
  __shared__ int tposS[2][4];
  __shared__ int ranksS[2][2][4];
  __shared__ unsigned int rawb[2][2];
  __shared__ unsigned int xbw[2][2];

  int tid = threadIdx.x;
  if (tid < NBITS) permS[tid] = perm[tid];
  if (tid < 2) {
    const void* tp = (tid == 0) ? tmap : traw;
    int c = 0;
    for (int b = 0; b < NBITS; b++)
      if (read_tpl(tp, b)) { if (c < 4) tposS[tid][c] = b; c++; }
  }
  if (tid < 4) { rawb[tid >> 1][tid & 1] = 0u; xbw[tid >> 1][tid & 1] = 0u; }
  __syncthreads();

  int rid = tid >> 7;
  int sub = tid & 127;
  int op  = sub >> 6;
  int b   = sub & 63;
  int row = blockIdx.x * 2 + rid;

  if (op == 0) xps[rid][b] = x[row * NBITS + permS[b]];
  uint32_t k0 = op ? kr0 : km0;
  uint32_t k1 = op ? kr1 : km1;
  uint32_t o0, o1;
  threefry2x32(k0, k1, 0u, (uint32_t)(row * NBITS + b), o0, o1);
  us[rid][op][b] = (o0 ^ o1) >> 9;
  __syncthreads();

  if (b < 4) {
    int tpos = tposS[op][b];
    unsigned int ut = us[rid][op][tpos];
    int cnt = 0;
    for (int j = 0; j < NBITS; j++) {
      unsigned int uj = us[rid][op][j];
      cnt += (uj < ut) || (uj == ut && j < tpos);
    }
    ranksS[rid][op][b] = cnt;
  }
  __syncthreads();

  float v = xps[rid][b];
  bool flip = (b == ranksS[rid][op][0]) | (b == ranksS[rid][op][1]) |
              (b == ranksS[rid][op][2]) | (b == ranksS[rid][op][3]);
  if (op == 0) {
    g_xp  [row * NBITS + b] = v;
    g_xmap[row * NBITS + b] = flip ? -v : v;
    if (v > 0.f) atomicOr(&xbw[rid][b >> 5], 1u << (b & 31));
  } else {
    bool bit = flip ? (v < 0.f) : (v > 0.f);
    if (bit) atomicOr(&rawb[rid][b >> 5], 1u << (b & 31));
  }
  __syncthreads();

  if (op == 1 && b < MG) {
    unsigned int w = rawb[rid][b >> 2];
    g_target[row * MG + b] = (unsigned char)((w >> ((b & 3) * 8)) & 0xffu);
  }
  if (op == 0 && b < 2) g_xbits[row * 2 + b] = xbw[rid][b];
}

// ---------------------------------------------------------------------------
// Kernel 3: active-class compaction + exact hamming sums. 1 warp / row.
// ---------------------------------------------------------------------------
__global__ void ham_kernel(const int* __restrict__ y) {
  int tid = threadIdx.x, w = tid >> 5, l = tid & 31;
  int row = blockIdx.x * 8 + w;
  unsigned int xb0 = g_xbits[row * 2], xb1 = g_xbits[row * 2 + 1];
  int K = 0;
  unsigned long long hs = 0ull;
  for (int cb = 0; cb < 128; cb += 32) {
    int c = cb + l;
    bool act = (c < NC) && (y[row * NC + c] > 0);
    unsigned int msk = __ballot_sync(0xffffffffu, act);
    if (act) {
      int pos = K + __popc(msk & ((1u << l) - 1u));
      g_act[row * NC + pos] = (unsigned char)c;
      hs += (unsigned long long)(__popc(xb0 ^ g_cbits[c * 2]) +
                                 __popc(xb1 ^ g_cbits[c * 2 + 1]));
    }
    K += __popc(msk);
  }
  if (l == 0) g_K[row] = K;
  for (int o = 16; o; o >>= 1)
    hs += __shfl_xor_sync(0xffffffffu, hs, o);
  if (l == 0) {
    atomicAdd(&g_hamSum, hs);
    atomicAdd(&g_actTot, (unsigned long long)K);
  }
}

// ---------------------------------------------------------------------------
// Kernel 4: fused batched MLP + losses. FFMA2, 16 rows x 128 cols per warp.
//
// CTA: 256 thr = 8 warps; 64 rows. Warp w: rg = w>>1 (rows [16rg,16rg+16)),
//   cg = w&1 (cols [128cg, 128cg+128)); lane l owns cols 128cg+4l..+3.
// Per warp-k: 1x LDS128 W (conflict-free) + 4 dup movs; 4x broadcast LDS128
//   of hT row-quads -> natural f32x2 row-pairs; 32 FFMA2.
// hT [k][row] stride 68 (16B-aligned rows). After GEMM2, logits (+b2) go to
//   a buffer aliasing hT ([row][264], conflict-free STS128), then warp w
//   reduces rows [8w, 8w+8).
// W2 staged as 16KB half-chunks, 2-deep cp.async ring. 112.6KB -> 2 CTAs/SM.
// ---------------------------------------------------------------------------
#define HSTRIDE  68
#define LSTRIDE  264
#define SM_W1S   0          // 2048 floats
#define SM_B1    2048       // 256
#define SM_B2    2304       // 256
#define SM_HT    2560       // 17408 (256 k * 68); logits alias (64 * 264)
#define SM_W2    19968      // 2 * 4096 (16KB half-chunks)
#define SM_FLOATS 28160     // 112640 bytes

__device__ __forceinline__ void ffma2(ull& d, ull a, ull b) {
  asm("fma.rn.f32x2 %0, %1, %2, %0;" : "+l"(d) : "l"(a), "l"(b));
}
__device__ __forceinline__ ull dup2(float v) {
  ull r;
  asm("mov.b64 %0, {%1, %1};" : "=l"(r) : "f"(v));
  return r;
}
__device__ __forceinline__ float2 unpack2(ull v) {
  float2 t;
  asm("mov.b64 {%0, %1}, %2;" : "=f"(t.x), "=f"(t.y) : "l"(v));
  return t;
}
__device__ __forceinline__ void cpasync16(float* s, const float* g) {
  unsigned sa = (unsigned)__cvta_generic_to_shared(s);
  asm volatile("cp.async.cg.shared.global [%0], [%1], 16;" :: "r"(sa), "l"(g));
}
__device__ __forceinline__ float fast_rcp(float d) {
  float r = __uint_as_float(0x7EF311C3u - __float_as_uint(d));
  r = r * (2.0f - d * r);
  r = r * (2.0f - d * r);
  r = r * (2.0f - d * r);
  return r;
}

__global__ void __launch_bounds__(256, 2)
mlp_kernel(const float* __restrict__ W1, const float* __restrict__ b1,
           const float* __restrict__ W2, const float* __restrict__ b2) {
  extern __shared__ float sm[];
  float* W1s    = sm + SM_W1S;
  float* b1s    = sm + SM_B1;
  float* b2s    = sm + SM_B2;
  float* hT     = sm + SM_HT;
  float* logits = sm + SM_HT;   // alias: hT dead after GEMM2 each m
  float* w2s    = sm + SM_W2;

  int tid = threadIdx.x, w = tid >> 5, l = tid & 31;
  int rg = w >> 1, cg = w & 1;
  int pass = blockIdx.y;
  int row0 = blockIdx.x * 64;
  const float* inp = (pass == 0) ? g_xmap : g_xp;

  // x rows of this warp's GEMM1 slice: lane l holds cols (2l, 2l+1) x 8 rows
  float xperm[16];
#pragma unroll
  for (int r = 0; r < 8; r++) {
    float2 t = *(const float2*)(inp + (row0 + w * 8 + r) * NBITS + 2 * l);
    xperm[2 * r] = t.x; xperm[2 * r + 1] = t.y;
  }

  // prefetch half-chunk 0 of W2 (16 k x 256 cols = 4096 floats)
  {
#pragma unroll
    for (int q = 0; q < 4; q++)
      cpasync16(w2s + (tid + q * 256) * 4, W2 + (tid + q * 256) * 4);
    asm volatile("cp.async.commit_group;");
  }

  double mapAcc = 0.0, netAcc = 0.0;
  unsigned int hitAcc = 0;

  for (int mm = 0; mm < MG; mm++) {
    __syncthreads();   // logits reads (prev m) done before W1s/hT overwritten
    {
      const float4* w1p = (const float4*)(W1 + mm * 2048);
      float4* w1d = (float4*)W1s;
      w1d[tid] = w1p[tid];
      w1d[tid + 256] = w1p[tid + 256];
      b1s[tid] = b1[mm * 256 + tid];
      b2s[tid] = b2[mm * 256 + tid];
    }
    __syncthreads();

    // ---- GEMM1: h = silu(xs @ W1 + b1) -> hT[k][row], stride 68 ----
    {
      float xv[8][8];
#pragma unroll
      for (int i = 0; i < 8; i++)
#pragma unroll
        for (int s = 0; s < 8; s++)
          xv[i][s] = __shfl_sync(0xffffffffu, xperm[2 * i + (s & 1)],
                                 mm * 4 + (s >> 1));
#pragma unroll
      for (int kk = 0; kk < 8; kk++) {
        int k = kk * 32 + l;
        float w1c[8];
#pragma unroll
        for (int s = 0; s < 8; s++) w1c[s] = W1s[s * 256 + k];
        float bk = b1s[k];
        float* hp = hT + k * HSTRIDE + 8 * w;
#pragma unroll
        for (int ip = 0; ip < 4; ip++) {
          float h2[2];
#pragma unroll
          for (int u = 0; u < 2; u++) {
            int i = 2 * ip + u;
            float a = bk;
#pragma unroll
            for (int s = 0; s < 8; s++) a = fmaf(xv[i][s], w1c[s], a);
            float t = __expf(-a);
            float d = 1.0f + fminf(t, 1e30f);
            h2[u] = a * fast_rcp(d);
          }
          *(float2*)(hp + 2 * ip) = make_float2(h2[0], h2[1]);
        }
      }
    }

    // ---- GEMM2: 16 rows x 128 cols per warp, FFMA2 row-pairs ----
    ull acc2[8][4];
#pragma unroll
    for (int i = 0; i < 8; i++)
#pragma unroll
      for (int j = 0; j < 4; j++) acc2[i][j] = 0ull;

    for (int hc = 0; hc < 16; hc++) {
      int g2 = mm * 16 + hc;
      if (g2 + 1 < 128) {
        const float* src = W2 + (g2 + 1) * 4096;
        float* dst = w2s + ((g2 + 1) & 1) * 4096;
#pragma unroll
        for (int q = 0; q < 4; q++)
          cpasync16(dst + (tid + q * 256) * 4, src + (tid + q * 256) * 4);
        asm volatile("cp.async.commit_group;");
        asm volatile("cp.async.wait_group 1;");
      } else {
        asm volatile("cp.async.wait_group 0;");
      }
      __syncthreads();   // also guards hT (GEMM1 stores) on first iteration

      const float* wch = w2s + (g2 & 1) * 4096 + 128 * cg + 4 * l;
      const float* hb  = hT + (hc * 16) * HSTRIDE + 16 * rg;
#pragma unroll 2
      for (int kk2 = 0; kk2 < 16; kk2++) {
        float4 wv = *(const float4*)(wch + kk2 * 256);
        ull wd0 = dup2(wv.x), wd1 = dup2(wv.y);
        ull wd2 = dup2(wv.z), wd3 = dup2(wv.w);
        const float* hk = hb + kk2 * HSTRIDE;
#pragma unroll
        for (int j = 0; j < 4; j++) {
          ulonglong2 hp = *(const ulonglong2*)(hk + 4 * j);
          ffma2(acc2[2 * j][0],     hp.x, wd0);
          ffma2(acc2[2 * j][1],     hp.x, wd1);
          ffma2(acc2[2 * j][2],     hp.x, wd2);
          ffma2(acc2[2 * j][3],     hp.x, wd3);
          ffma2(acc2[2 * j + 1][0], hp.y, wd0);
          ffma2(acc2[2 * j + 1][1], hp.y, wd1);
          ffma2(acc2[2 * j + 1][2], hp.y, wd2);
          ffma2(acc2[2 * j + 1][3], hp.y, wd3);
        }
      }
      __syncthreads();
    }

    // ---- epilogue: logits (+bias) to smem, then per-row reductions ----
    {
      float4 bA = *(const float4*)(b2s + 128 * cg + 4 * l);
      float* lbase = logits + 128 * cg + 4 * l;
#pragma unroll
      for (int rp = 0; rp < 8; rp++) {
        float2 t0 = unpack2(acc2[rp][0]);
        float2 t1 = unpack2(acc2[rp][1]);
        float2 t2 = unpack2(acc2[rp][2]);
        float2 t3 = unpack2(acc2[rp][3]);
        int r0 = 16 * rg + 2 * rp;
        *(float4*)(lbase + r0 * LSTRIDE) =
            make_float4(t0.x + bA.x, t1.x + bA.y, t2.x + bA.z, t3.x + bA.w);
        *(float4*)(lbase + (r0 + 1) * LSTRIDE) =
            make_float4(t0.y + bA.x, t1.y + bA.y, t2.y + bA.z, t3.y + bA.w);
      }
    }
    __syncthreads();

    for (int i = 0; i < 8; i++) {
      int lrow = w * 8 + i;
      int grow = row0 + lrow;
      float v[8];
      {
        float4 va = *(const float4*)(logits + lrow * LSTRIDE + 8 * l);
        float4 vb = *(const float4*)(logits + lrow * LSTRIDE + 8 * l + 4);
        v[0] = va.x; v[1] = va.y; v[2] = va.z; v[3] = va.w;
        v[4] = vb.x; v[5] = vb.y; v[6] = vb.z; v[7] = vb.w;
      }
      float mx = v[0]; int ai = 8 * l;
#pragma unroll
      for (int j = 1; j < 8; j++)
        if (v[j] > mx) { mx = v[j]; ai = 8 * l + j; }
      for (int o = 16; o; o >>= 1) {
        float vm = __shfl_xor_sync(0xffffffffu, mx, o);
        int   vi = __shfl_xor_sync(0xffffffffu, ai, o);
        if (vm > mx || (vm == mx && vi < ai)) { mx = vm; ai = vi; }
      }
      float se = 0.f;
#pragma unroll
      for (int j = 0; j < 8; j++) se += __expf(v[j] - mx);
      for (int o = 16; o; o >>= 1)
        se += __shfl_xor_sync(0xffffffffu, se, o);
      float lse = mx + __logf(se);
      __syncwarp();

      if (pass == 0) {
        if (l == 0) {
          int tgt = g_target[grow * MG + mm];
          mapAcc += (double)(lse - logits[lrow * LSTRIDE + tgt]);
          hitAcc += (ai == tgt) ? 1u : 0u;
        }
      } else {
        int K = g_K[grow];
        const unsigned char* al = g_act + grow * NC;
        double gs = 0.0;
        for (int ci = l; ci < K; ci += 32)
          gs += (double)logits[lrow * LSTRIDE + g_ct[al[ci] * MG + mm]];
        for (int o = 16; o; o >>= 1)
          gs += __shfl_xor_sync(0xffffffffu, gs, o);
        if (l == 0) netAcc += (double)lse - gs / (double)K;
      }
      __syncwarp();
    }
  }

  if (l == 0) {
    if (pass == 0) {
      atomicAdd(&g_mapSum, mapAcc);
      atomicAdd(&g_hits, (unsigned long long)hitAcc);
    } else {
      atomicAdd(&g_netSum, netAcc);
    }
  }
}

// ---------------------------------------------------------------------------
// Kernel 5: finalize 5 scalars
// ---------------------------------------------------------------------------
__global__ void finalize_kernel(float* out) {
  if (threadIdx.x == 0) {
    double net = g_netSum / (double)NS;
    double map = g_mapSum / (double)NS;
    out[0] = (float)(net + map);
    out[1] = (float)net;
    out[2] = (float)map;
    out[3] = (float)((double)g_hits / ((double)NS * (double)MG));
    out[4] = (float)((double)g_hamSum / (double)g_actTot);
  }
}

// ---------------------------------------------------------------------------
extern "C" void kernel_launch(void* const* d_in, const int* in_sizes, int n_in,
                              void* d_out, int out_size) {
  const float* x    = (const float*)d_in[0];
  const int*   y    = (const int*)  d_in[1];
  const float* cen  = (const float*)d_in[2];
  const int*   perm = (const int*)  d_in[3];
  const void*  tmap = d_in[4];
  const void*  traw = d_in[5];
  const float* W1   = (const float*)d_in[6];
  const float* b1   = (const float*)d_in[7];
  const float* W2   = (const float*)d_in[8];
  const float* b2   = (const float*)d_in[9];
  float* out = (float*)d_out;

  uint32_t km0, km1, kr0, kr1;
  threefry2x32(0u, 1u, 0u, 0u, km0, km1);
  threefry2x32(0u, 1u, 0u, 1u, kr0, kr1);

  cudaFuncSetAttribute(mlp_kernel, cudaFuncAttributeMaxDynamicSharedMemorySize,
                       SM_FLOATS * 4);

  setup_kernel<<<1, 128>>>(cen, perm, (const unsigned char*)tmap,
                           (const unsigned char*)traw);
  prep_kernel<<<NS / 2, 256>>>(x, perm, tmap, traw, km0, km1, kr0, kr1);
  ham_kernel<<<NS / 8, 256>>>(y);
  dim3 grid(NS / 64, 2);
  mlp_kernel<<<grid, 256, SM_FLOATS * 4>>>(W1, b1, W2, b2);
  finalize_kernel<<<1, 32>>>(out);
  (void)in_sizes; (void)n_in; (void)out_size;
}